// round 5
// baseline (speedup 1.0000x reference)
#include <cuda_runtime.h>

#define BB 8
#define T 32768
#define R 64
#define S 128
#define NBLK 24
#define TT 128   // timestep tile per CTA

typedef unsigned long long u64;

// Persistent scratch: ping-pong h + skip accumulator + duplicated transposed weights.
__device__ __align__(16) float g_h[2][BB * R * T];   // 2 x 64 MB
__device__ __align__(16) float g_skip[BB * S * T];   // 128 MB
// Duplicated ({w,w} pairs) transposed weights for packed f32x2 FMA:
//   g_wcT2 [l][ci][k][co]x2   row = 256 floats (128 u64)
//   g_wfg2 [l][ci][co']x2     co'<64: filter, co'>=64: gate
//   g_wrs2 [l][ci][co']x2     co'<64: res,    co'>=64: skip
__device__ __align__(16) float g_wcT2[NBLK * R * 256];
__device__ __align__(16) float g_wfg2[NBLK * R * 256];
__device__ __align__(16) float g_wrs2[NBLK * R * 384];

#define PRE1 (NBLK * R * 256)
#define PRE2 (NBLK * R * 256)
#define PRE3 (NBLK * R * 384)

#define FFMA2(d, a, b) asm("fma.rn.f32x2 %0, %1, %2, %0;" : "+l"(d) : "l"(a), "l"(b))
#define ADD2(d, a, b)  asm("add.rn.f32x2 %0, %1, %2;" : "=l"(d) : "l"(a), "l"(b))

__device__ __forceinline__ u64 pack2(float lo, float hi) {
    u64 v; asm("mov.b64 %0, {%1,%2};" : "=l"(v) : "f"(lo), "f"(hi)); return v;
}
__device__ __forceinline__ float2 unpack2(u64 v) {
    float2 r; asm("mov.b64 {%0,%1}, %2;" : "=f"(r.x), "=f"(r.y) : "l"(v)); return r;
}

__device__ __forceinline__ void fma4(float4 &a, float w, const float4 &v) {
    a.x = fmaf(w, v.x, a.x);
    a.y = fmaf(w, v.y, a.y);
    a.z = fmaf(w, v.z, a.z);
    a.w = fmaf(w, v.w, a.w);
}

__device__ __forceinline__ float sigf(float x) { return 1.f / (1.f + expf(-x)); }

// ---------------------------------------------------------------------------
// Prep: build duplicated transposed weight layouts (once per launch)
// ---------------------------------------------------------------------------
__global__ void prep_kernel(const float* __restrict__ wc, const float* __restrict__ wf,
                            const float* __restrict__ wg, const float* __restrict__ wr,
                            const float* __restrict__ ws) {
    int idx = blockIdx.x * blockDim.x + threadIdx.x;
    if (idx < PRE1) {
        int e = idx >> 1;
        int l = e >> 13, r = e & 8191;
        int ci = r >> 7, k = (r >> 6) & 1, co = r & 63;
        g_wcT2[idx] = wc[(((size_t)l * 64 + co) * 64 + ci) * 2 + k];
        return;
    }
    idx -= PRE1;
    if (idx < PRE2) {
        int e = idx >> 1;
        int l = e >> 13, r = e & 8191;
        int ci = r >> 7, cp = r & 127;
        g_wfg2[idx] = (cp < 64) ? wf[((size_t)l * 64 + cp) * 64 + ci]
                                : wg[((size_t)l * 64 + cp - 64) * 64 + ci];
        return;
    }
    idx -= PRE2;
    if (idx < PRE3) {
        int e = idx >> 1;
        int l = e / (64 * 192), r = e % (64 * 192);
        int ci = r / 192, cp = r % 192;
        g_wrs2[idx] = (cp < 64) ? wr[((size_t)l * 64 + cp) * 64 + ci]
                                : ws[((size_t)l * 128 + cp - 64) * 64 + ci];
    }
}

// ---------------------------------------------------------------------------
// Kernel 1: input 1x1 conv  h[b][r][t] = w_in[r] * x[b][t] + b_in[r]
// ---------------------------------------------------------------------------
__global__ void input_kernel(const float* __restrict__ x,
                             const float* __restrict__ w_in,
                             const float* __restrict__ b_in) {
    int idx = blockIdx.x * blockDim.x + threadIdx.x;   // [0, B*R*T)
    int t = idx & (T - 1);
    int r = (idx >> 15) & (R - 1);
    int b = idx >> 21;
    g_h[0][idx] = fmaf(__ldg(&w_in[r]), __ldg(&x[b * T + t]), __ldg(&b_in[r]));
}

// ---------------------------------------------------------------------------
// Kernel 2: fused WaveNet block with packed f32x2 FMAs.
// ---------------------------------------------------------------------------
__global__ void __launch_bounds__(256, 2) block_kernel(
    const float* __restrict__ h_in, float* __restrict__ h_out,
    const float* __restrict__ wcT, const float* __restrict__ bc,
    const float* __restrict__ wfg, const float* __restrict__ bf,
    const float* __restrict__ bg,
    const float* __restrict__ wrs, const float* __restrict__ br,
    const float* __restrict__ bs,
    int d, int first)
{
    extern __shared__ float smem[];
    float* hn = smem;              // [R][TT] h at t
    float* hp = smem + R * TT;     // [R][TT] h at t-d; reused as 'a' after phase 2
    float* zz = smem + 2 * R * TT; // [R][TT] z

    const int b  = blockIdx.y;
    const int t0 = blockIdx.x * TT;
    const int tid = threadIdx.x;
    const int wp = tid >> 5, l = tid & 31;
    const float* hbase = h_in + (size_t)b * R * T;

    // ---- Phase 0: cooperative loads ----
    for (int f = tid; f < R * TT / 4; f += 256) {
        int row = f >> 5;            // TT/4 = 32 float4 per row
        int col = f & 31;
        ((float4*)hn)[f] = ((const float4*)(hbase + (size_t)row * T + t0))[col];
    }
    if ((d & 3) == 0) {
        const int dq = d >> 2;
        for (int f = tid; f < R * 32; f += 256) {
            int row = f >> 5, col = f & 31;
            int tq = (t0 >> 2) + col - dq;
            float4 v = (tq >= 0) ? ((const float4*)(hbase + (size_t)row * T))[tq]
                                 : make_float4(0.f, 0.f, 0.f, 0.f);
            ((float4*)hp)[f] = v;
        }
    } else {
        for (int idx = tid; idx < R * TT; idx += 256) {
            int row = idx >> 7;
            int col = idx & 127;
            int t = t0 + col - d;
            hp[idx] = (t >= 0) ? hbase[(size_t)row * T + t] : 0.f;
        }
    }
    __syncthreads();

    const ulonglong2* hn2 = (const ulonglong2*)hn;
    const ulonglong2* hp2 = (const ulonglong2*)hp;
    ulonglong2* z2 = (ulonglong2*)zz;
    ulonglong2* a2 = (ulonglong2*)hp;   // reuse
    const float4* hn4 = (const float4*)hn;

    const int co0 = wp << 3;            // this warp's 8 output channels

    // ---- Phase 1: z = causal conv (8 co/warp, dup weights [ci][k][co]x2) ----
    {
        const ulonglong2* wc2 = (const ulonglong2*)wcT;   // 64 ulonglong2 per ci row
        u64 aL[8], aH[8];
        #pragma unroll
        for (int j = 0; j < 8; j++) { aL[j] = 0ull; aH[j] = 0ull; }
        #pragma unroll 4
        for (int ci = 0; ci < R; ci++) {
            ulonglong2 p = hp2[(ci << 5) + l];
            ulonglong2 n = hn2[(ci << 5) + l];
            const ulonglong2* w0 = wc2 + ci * 64 + (co0 >> 1);        // prev tap
            const ulonglong2* w1 = w0 + 32;                            // cur tap
            #pragma unroll
            for (int q = 0; q < 4; q++) {
                ulonglong2 wa = __ldg(&w0[q]);
                ulonglong2 wb = __ldg(&w1[q]);
                FFMA2(aL[2*q],   wa.x, p.x); FFMA2(aH[2*q],   wa.x, p.y);
                FFMA2(aL[2*q+1], wa.y, p.x); FFMA2(aH[2*q+1], wa.y, p.y);
                FFMA2(aL[2*q],   wb.x, n.x); FFMA2(aH[2*q],   wb.x, n.y);
                FFMA2(aL[2*q+1], wb.y, n.x); FFMA2(aH[2*q+1], wb.y, n.y);
            }
        }
        #pragma unroll
        for (int j = 0; j < 8; j++) {
            int co = co0 + j;
            float bv = __ldg(&bc[co]);
            u64 bb = pack2(bv, bv);
            u64 rl, rh; ADD2(rl, aL[j], bb); ADD2(rh, aH[j], bb);
            ulonglong2 o; o.x = rl; o.y = rh;
            z2[(co << 5) + l] = o;
        }
    }
    __syncthreads();

    // ---- Phase 2: a = tanh(Wf z + bf) * sigmoid(Wg z + bg) ----
    {
        const ulonglong2* w2 = (const ulonglong2*)wfg;
        u64 fL[8], fH[8], gL[8], gH[8];
        #pragma unroll
        for (int j = 0; j < 8; j++) { fL[j]=0ull; fH[j]=0ull; gL[j]=0ull; gH[j]=0ull; }
        #pragma unroll 2
        for (int ci = 0; ci < R; ci++) {
            ulonglong2 zv = z2[(ci << 5) + l];
            const ulonglong2* wF = w2 + ci * 64 + (co0 >> 1);
            const ulonglong2* wG = wF + 32;
            #pragma unroll
            for (int q = 0; q < 4; q++) {
                ulonglong2 wf_ = __ldg(&wF[q]);
                ulonglong2 wg_ = __ldg(&wG[q]);
                FFMA2(fL[2*q],   wf_.x, zv.x); FFMA2(fH[2*q],   wf_.x, zv.y);
                FFMA2(fL[2*q+1], wf_.y, zv.x); FFMA2(fH[2*q+1], wf_.y, zv.y);
                FFMA2(gL[2*q],   wg_.x, zv.x); FFMA2(gH[2*q],   wg_.x, zv.y);
                FFMA2(gL[2*q+1], wg_.y, zv.x); FFMA2(gH[2*q+1], wg_.y, zv.y);
            }
        }
        __syncthreads();   // all reads of z & hp done before a overwrites hp
        #pragma unroll
        for (int j = 0; j < 8; j++) {
            int co = co0 + j;
            float bfv = __ldg(&bf[co]);
            float bgv = __ldg(&bg[co]);
            float2 f0 = unpack2(fL[j]), f1 = unpack2(fH[j]);
            float2 g0 = unpack2(gL[j]), g1 = unpack2(gH[j]);
            float ox = tanhf(f0.x + bfv) * sigf(g0.x + bgv);
            float oy = tanhf(f0.y + bfv) * sigf(g0.y + bgv);
            float oz = tanhf(f1.x + bfv) * sigf(g1.x + bgv);
            float ow = tanhf(f1.y + bfv) * sigf(g1.y + bgv);
            ulonglong2 o; o.x = pack2(ox, oy); o.y = pack2(oz, ow);
            a2[(co << 5) + l] = o;
        }
    }
    __syncthreads();

    // ---- Phase 3: fused res + skip over 192 dup rows (12 co' x 2 chunks/warp) ----
    {
        const ulonglong2* w2 = (const ulonglong2*)wrs;    // 96 ulonglong2 per ci row
        float* hdst = h_out + (size_t)b * R * T + t0;
        float* skp  = g_skip + (size_t)b * S * T + t0;
        #pragma unroll
        for (int chunk = 0; chunk < 2; chunk++) {
            const int c0 = wp * 24 + chunk * 12;       // 12 consecutive co'
            u64 aL[12], aH[12];
            #pragma unroll
            for (int j = 0; j < 12; j++) { aL[j] = 0ull; aH[j] = 0ull; }
            #pragma unroll 2
            for (int ci = 0; ci < R; ci++) {
                ulonglong2 av = a2[(ci << 5) + l];
                const ulonglong2* wr_ = w2 + ci * 96 + (c0 >> 1);
                #pragma unroll
                for (int q = 0; q < 6; q++) {
                    ulonglong2 w = __ldg(&wr_[q]);
                    FFMA2(aL[2*q],   w.x, av.x); FFMA2(aH[2*q],   w.x, av.y);
                    FFMA2(aL[2*q+1], w.y, av.x); FFMA2(aH[2*q+1], w.y, av.y);
                }
            }
            #pragma unroll
            for (int j = 0; j < 12; j++) {
                int cp = c0 + j;
                if (cp < 64) {
                    // residual: h_out = h_in + Wr a + br
                    float bv = __ldg(&br[cp]);
                    u64 bb = pack2(bv, bv);
                    float4 hv = hn4[(cp << 5) + l];
                    u64 rl, rh, sl, sh;
                    ADD2(rl, aL[j], bb); ADD2(rh, aH[j], bb);
                    ADD2(sl, rl, pack2(hv.x, hv.y)); ADD2(sh, rh, pack2(hv.z, hv.w));
                    ulonglong2 o; o.x = sl; o.y = sh;
                    ((ulonglong2*)(hdst + (size_t)cp * T))[l] = o;
                } else {
                    int s = cp - 64;
                    float bv = __ldg(&bs[s]);
                    u64 bb = pack2(bv, bv);
                    u64 rl, rh;
                    ADD2(rl, aL[j], bb); ADD2(rh, aH[j], bb);
                    ulonglong2* gp = (ulonglong2*)(skp + (size_t)s * T) + l;
                    if (!first) {
                        ulonglong2 o = *gp;
                        ADD2(rl, rl, o.x); ADD2(rh, rh, o.y);
                    }
                    ulonglong2 o; o.x = rl; o.y = rh;
                    *gp = o;
                }
            }
        }
    }
}

// ---------------------------------------------------------------------------
// Kernel 3: head.  out = W2 relu(W1 relu(skip) + b1) + b2
// ---------------------------------------------------------------------------
__global__ void __launch_bounds__(256) head_kernel(
    const float* __restrict__ w1, const float* __restrict__ b1,
    const float* __restrict__ w2, const float* __restrict__ b2,
    float* __restrict__ out)
{
    extern __shared__ float smem[];
    float* sk   = smem;            // [S][TT] relu(skip)
    float* part = smem + S * TT;   // [8][TT] per-warp partials

    const int b  = blockIdx.y;
    const int t0 = blockIdx.x * TT;
    const int tid = threadIdx.x, wp = tid >> 5, l = tid & 31;
    const float* skg = g_skip + (size_t)b * S * T + t0;

    for (int f = tid; f < S * TT / 4; f += 256) {
        int row = f >> 5, col = f & 31;
        float4 v = ((const float4*)(skg + (size_t)row * T))[col];
        v.x = fmaxf(v.x, 0.f); v.y = fmaxf(v.y, 0.f);
        v.z = fmaxf(v.z, 0.f); v.w = fmaxf(v.w, 0.f);
        ((float4*)sk)[f] = v;
    }
    __syncthreads();

    const float4* sk4 = (const float4*)sk;
    float4 po = {0.f, 0.f, 0.f, 0.f};
    for (int s2 = wp * 16; s2 < wp * 16 + 16; s2++) {
        float4 u = {0.f, 0.f, 0.f, 0.f};
        const float* wrow = w1 + (s2 << 7);
        #pragma unroll 8
        for (int s1 = 0; s1 < S; s1++)
            fma4(u, __ldg(wrow + s1), sk4[(s1 << 5) + l]);
        float bb = __ldg(b1 + s2);
        u.x = fmaxf(u.x + bb, 0.f); u.y = fmaxf(u.y + bb, 0.f);
        u.z = fmaxf(u.z + bb, 0.f); u.w = fmaxf(u.w + bb, 0.f);
        fma4(po, __ldg(w2 + s2), u);
    }
    ((float4*)(part + wp * TT))[l] = po;
    __syncthreads();

    if (tid < TT) {
        float acc = __ldg(b2);
        #pragma unroll
        for (int ww = 0; ww < 8; ww++) acc += part[ww * TT + tid];
        out[(size_t)b * T + t0 + tid] = acc;   // output layout [B, T, 1]
    }
}

// ---------------------------------------------------------------------------
extern "C" void kernel_launch(void* const* d_in, const int* in_sizes, int n_in,
                              void* d_out, int out_size) {
    const float* x        = (const float*)d_in[0];
    const float* w_in     = (const float*)d_in[1];
    const float* b_in     = (const float*)d_in[2];
    const float* w_causal = (const float*)d_in[3];
    const float* b_causal = (const float*)d_in[4];
    const float* w_filter = (const float*)d_in[5];
    const float* b_filter = (const float*)d_in[6];
    const float* w_gate   = (const float*)d_in[7];
    const float* b_gate   = (const float*)d_in[8];
    const float* w_res    = (const float*)d_in[9];
    const float* b_res    = (const float*)d_in[10];
    const float* w_skip   = (const float*)d_in[11];
    const float* b_skip   = (const float*)d_in[12];
    const float* w_out1   = (const float*)d_in[13];
    const float* b_out1   = (const float*)d_in[14];
    const float* w_out2   = (const float*)d_in[15];
    const float* b_out2   = (const float*)d_in[16];
    float* out = (float*)d_out;

    const int blk_smem  = 3 * R * TT * 4;            // 96 KB
    const int head_smem = (S * TT + 8 * TT) * 4;     // 68 KB
    cudaFuncSetAttribute(block_kernel, cudaFuncAttributeMaxDynamicSharedMemorySize, blk_smem);
    cudaFuncSetAttribute(head_kernel,  cudaFuncAttributeMaxDynamicSharedMemorySize, head_smem);

    float* hbuf0; float* wct; float* wfg; float* wrs;
    cudaGetSymbolAddress((void**)&hbuf0, g_h);
    cudaGetSymbolAddress((void**)&wct, g_wcT2);
    cudaGetSymbolAddress((void**)&wfg, g_wfg2);
    cudaGetSymbolAddress((void**)&wrs, g_wrs2);
    float* hbuf[2] = { hbuf0, hbuf0 + (size_t)BB * R * T };

    const int pre_total = PRE1 + PRE2 + PRE3;
    prep_kernel<<<(pre_total + 255) / 256, 256>>>(w_causal, w_filter, w_gate, w_res, w_skip);

    input_kernel<<<BB * R * T / 256, 256>>>(x, w_in, b_in);

    dim3 grid(T / TT, BB);
    for (int i = 0; i < NBLK; i++) {
        int d = 1 << (i & 7);   // dilations 1..128, repeated 3x
        block_kernel<<<grid, 256, blk_smem>>>(
            hbuf[i & 1], hbuf[(i + 1) & 1],
            wct + (size_t)i * R * 256, b_causal + (size_t)i * R,
            wfg + (size_t)i * R * 256, b_filter + (size_t)i * R, b_gate + (size_t)i * R,
            wrs + (size_t)i * R * 384, b_res + (size_t)i * R, b_skip + (size_t)i * S,
            d, i == 0 ? 1 : 0);
    }

    head_kernel<<<grid, 256, head_smem>>>(w_out1, b_out1, w_out2, b_out2, out);
}

// round 6
// speedup vs baseline: 2.2327x; 2.2327x over previous
#include <cuda_runtime.h>

#define BB 8
#define T 32768
#define R 64
#define S 128
#define NBLK 24
#define TT 128
#define AST 132   // smem activation row stride (conflict-free for mma B frags)

typedef unsigned int u32;

__device__ __align__(16) float g_h[2][BB * R * T];   // ping-pong fp32 residual stream
__device__ __align__(16) float g_skip[BB * S * T];   // fp32 skip accumulator

// Fragment-ordered tf32 weights, hi + lo split (built once per launch by prep_kernel).
// P1: conv  [M=64,K=128] -> 4 slabs x 16 ktiles x 32 lanes x 4 regs
// P2: f|g   [M=128,K=64] -> 8 slabs x 8 ktiles  (slab rows 0-7 filter ch, 8-15 gate ch)
// P3: r|s   [M=192,K=64] -> 12 slabs x 8 ktiles
#define P1N 8192
#define P2N 8192
#define P3N 12288
__device__ __align__(16) float g_p1h[NBLK * P1N], g_p1l[NBLK * P1N];
__device__ __align__(16) float g_p2h[NBLK * P2N], g_p2l[NBLK * P2N];
__device__ __align__(16) float g_p3h[NBLK * P3N], g_p3l[NBLK * P3N];

__device__ __forceinline__ float tf32r(float x) {
    u32 o; asm("cvt.rna.tf32.f32 %0, %1;" : "=r"(o) : "f"(x));
    return __uint_as_float(o);
}
__device__ __forceinline__ float sigf(float x) { return 1.f / (1.f + expf(-x)); }

#define MMA(d, a, b0, b1) \
    asm("mma.sync.aligned.m16n8k8.row.col.f32.tf32.tf32.f32 " \
        "{%0,%1,%2,%3}, {%4,%5,%6,%7}, {%8,%9}, {%0,%1,%2,%3};" \
        : "+f"(d[0]), "+f"(d[1]), "+f"(d[2]), "+f"(d[3]) \
        : "r"(a.x), "r"(a.y), "r"(a.z), "r"(a.w), "r"(b0), "r"(b1))

__device__ __forceinline__ void fma4(float4 &a, float w, const float4 &v) {
    a.x = fmaf(w, v.x, a.x); a.y = fmaf(w, v.y, a.y);
    a.z = fmaf(w, v.z, a.z); a.w = fmaf(w, v.w, a.w);
}

// ---------------------------------------------------------------------------
// Prep: build fragment-ordered hi/lo tf32 weights
// ---------------------------------------------------------------------------
__global__ void prep_kernel(const float* __restrict__ wc, const float* __restrict__ wf,
                            const float* __restrict__ wg, const float* __restrict__ wr,
                            const float* __restrict__ ws) {
    int idx = blockIdx.x * blockDim.x + threadIdx.x;
    const int PER = P1N + P2N + P3N;
    if (idx >= NBLK * PER) return;
    int lyr = idx / PER;
    int e = idx % PER;
    float w; float *dh, *dl;
    if (e < P1N) {
        int slab = e >> 11, kt = (e >> 7) & 15, lane = (e >> 2) & 31, r = e & 3;
        int row = slab * 16 + (lane >> 2) + 8 * (r & 1);
        int k = kt * 8 + (lane & 3) + 4 * (r >> 1);
        w = (k < 64) ? wc[(((size_t)lyr * 64 + row) * 64 + k) * 2]
                     : wc[(((size_t)lyr * 64 + row) * 64 + (k - 64)) * 2 + 1];
        dh = g_p1h + (size_t)lyr * P1N + e;
        dl = g_p1l + (size_t)lyr * P1N + e;
    } else if (e < P1N + P2N) {
        int e2 = e - P1N;
        int slab = e2 >> 10, kt = (e2 >> 7) & 7, lane = (e2 >> 2) & 31, r = e2 & 3;
        int ch = slab * 8 + (lane >> 2);
        int k = kt * 8 + (lane & 3) + 4 * (r >> 1);
        w = ((r & 1) == 0) ? wf[((size_t)lyr * 64 + ch) * 64 + k]
                           : wg[((size_t)lyr * 64 + ch) * 64 + k];
        dh = g_p2h + (size_t)lyr * P2N + e2;
        dl = g_p2l + (size_t)lyr * P2N + e2;
    } else {
        int e3 = e - P1N - P2N;
        int slab = e3 >> 10, kt = (e3 >> 7) & 7, lane = (e3 >> 2) & 31, r = e3 & 3;
        int cp = slab * 16 + (lane >> 2) + 8 * (r & 1);
        int k = kt * 8 + (lane & 3) + 4 * (r >> 1);
        w = (cp < 64) ? wr[((size_t)lyr * 64 + cp) * 64 + k]
                      : ws[((size_t)lyr * 128 + (cp - 64)) * 64 + k];
        dh = g_p3h + (size_t)lyr * P3N + e3;
        dl = g_p3l + (size_t)lyr * P3N + e3;
    }
    float hi = tf32r(w);
    *dh = hi;
    *dl = tf32r(w - hi);
}

// ---------------------------------------------------------------------------
// Kernel 1: input 1x1 conv
// ---------------------------------------------------------------------------
__global__ void input_kernel(const float* __restrict__ x,
                             const float* __restrict__ w_in,
                             const float* __restrict__ b_in) {
    int idx = blockIdx.x * blockDim.x + threadIdx.x;
    int t = idx & (T - 1);
    int r = (idx >> 15) & (R - 1);
    int b = idx >> 21;
    g_h[0][idx] = fmaf(__ldg(&w_in[r]), __ldg(&x[b * T + t]), __ldg(&b_in[r]));
}

// ---------------------------------------------------------------------------
// Kernel 2: fused WaveNet block on tensor cores (tf32, weights hi+lo)
// ---------------------------------------------------------------------------
__global__ void __launch_bounds__(256, 2) block_kernel(
    const float* __restrict__ h_in, float* __restrict__ h_out,
    const uint4* __restrict__ p1h, const uint4* __restrict__ p1l, const float* __restrict__ bc,
    const uint4* __restrict__ p2h, const uint4* __restrict__ p2l, const float* __restrict__ bf,
    const float* __restrict__ bg,
    const uint4* __restrict__ p3h, const uint4* __restrict__ p3l, const float* __restrict__ br,
    const float* __restrict__ bs,
    int d, int first)
{
    extern __shared__ float sm[];
    float* s_hn = sm;                 // [64][AST] tf32-rounded h(t)
    float* s_hp = sm + 64 * AST;      // [64][AST] tf32-rounded h(t-d); reused as a
    float* s_z  = sm + 2 * 64 * AST;  // [64][AST] tf32-rounded z

    const int b = blockIdx.y, t0 = blockIdx.x * TT;
    const int tid = threadIdx.x, wp = tid >> 5, l = tid & 31;
    const int lk = l & 3, ln = l >> 2;       // B-frag k row / n col within tile
    const float* hbase = h_in + (size_t)b * R * T;

    // ---- Phase 0: load + tf32-round activation tiles ----
    for (int f = tid; f < R * 32; f += 256) {
        int row = f >> 5, c4 = f & 31;
        float4 v = ((const float4*)(hbase + (size_t)row * T + t0))[c4];
        float* p = s_hn + row * AST + c4 * 4;
        p[0] = tf32r(v.x); p[1] = tf32r(v.y); p[2] = tf32r(v.z); p[3] = tf32r(v.w);
    }
    if ((d & 3) == 0) {
        const int dq = d >> 2;
        for (int f = tid; f < R * 32; f += 256) {
            int row = f >> 5, c4 = f & 31;
            int tq = (t0 >> 2) + c4 - dq;
            float4 v = (tq >= 0) ? ((const float4*)(hbase + (size_t)row * T))[tq]
                                 : make_float4(0.f, 0.f, 0.f, 0.f);
            float* p = s_hp + row * AST + c4 * 4;
            p[0] = tf32r(v.x); p[1] = tf32r(v.y); p[2] = tf32r(v.z); p[3] = tf32r(v.w);
        }
    } else {
        for (int idx = tid; idx < R * TT; idx += 256) {
            int row = idx >> 7, col = idx & 127;
            int t = t0 + col - d;
            s_hp[row * AST + col] = (t >= 0) ? tf32r(hbase[(size_t)row * T + t]) : 0.f;
        }
    }
    __syncthreads();

    // ---- Phase 1: z = Wc x [hp; hn]  (M=64, K=128) ----
    {
        const int slab = wp >> 1, nb = (wp & 1) * 64;
        float acc[8][4];
        #pragma unroll
        for (int nt = 0; nt < 8; nt++)
            acc[nt][0] = acc[nt][1] = acc[nt][2] = acc[nt][3] = 0.f;
        #pragma unroll 4
        for (int kt = 0; kt < 16; kt++) {
            uint4 Ah = __ldg(&p1h[(slab * 16 + kt) * 32 + l]);
            uint4 Al = __ldg(&p1l[(slab * 16 + kt) * 32 + l]);
            const float* bp = ((kt < 8) ? s_hp + kt * 8 * AST
                                        : s_hn + (kt - 8) * 8 * AST) + lk * AST + ln + nb;
            #pragma unroll
            for (int nt = 0; nt < 8; nt++) {
                u32 b0 = __float_as_uint(bp[nt * 8]);
                u32 b1 = __float_as_uint(bp[4 * AST + nt * 8]);
                MMA(acc[nt], Ah, b0, b1);
                MMA(acc[nt], Al, b0, b1);
            }
        }
        int r0 = slab * 16 + ln;
        float bv0 = __ldg(bc + r0), bv1 = __ldg(bc + r0 + 8);
        #pragma unroll
        for (int nt = 0; nt < 8; nt++) {
            int c0 = nb + nt * 8 + 2 * lk;
            float2 v0 = { tf32r(acc[nt][0] + bv0), tf32r(acc[nt][1] + bv0) };
            float2 v1 = { tf32r(acc[nt][2] + bv1), tf32r(acc[nt][3] + bv1) };
            *(float2*)(s_z + r0 * AST + c0) = v0;
            *(float2*)(s_z + (r0 + 8) * AST + c0) = v1;
        }
    }
    __syncthreads();

    // ---- Phase 2: a = tanh(Wf z + bf) * sigmoid(Wg z + bg)  (M=128, K=64) ----
    // Slab rows 0-7 = filter ch, 8-15 = gate ch -> pair lands in one thread's c-regs.
    #pragma unroll
    for (int ui = 0; ui < 2; ui++) {
        int u = wp + ui * 8;
        int slab = u >> 1, nb = (u & 1) * 64;
        float acc[8][4];
        #pragma unroll
        for (int nt = 0; nt < 8; nt++)
            acc[nt][0] = acc[nt][1] = acc[nt][2] = acc[nt][3] = 0.f;
        #pragma unroll 2
        for (int kt = 0; kt < 8; kt++) {
            uint4 Ah = __ldg(&p2h[(slab * 8 + kt) * 32 + l]);
            uint4 Al = __ldg(&p2l[(slab * 8 + kt) * 32 + l]);
            const float* bp = s_z + (kt * 8 + lk) * AST + ln + nb;
            #pragma unroll
            for (int nt = 0; nt < 8; nt++) {
                u32 b0 = __float_as_uint(bp[nt * 8]);
                u32 b1 = __float_as_uint(bp[4 * AST + nt * 8]);
                MMA(acc[nt], Ah, b0, b1);
                MMA(acc[nt], Al, b0, b1);
            }
        }
        int ch = slab * 8 + ln;
        float bfv = __ldg(bf + ch), bgv = __ldg(bg + ch);
        #pragma unroll
        for (int nt = 0; nt < 8; nt++) {
            int c0 = nb + nt * 8 + 2 * lk;
            float a0 = tanhf(acc[nt][0] + bfv) * sigf(acc[nt][2] + bgv);
            float a1 = tanhf(acc[nt][1] + bfv) * sigf(acc[nt][3] + bgv);
            float2 v = { tf32r(a0), tf32r(a1) };
            *(float2*)(s_hp + ch * AST + c0) = v;   // a overwrites hp
        }
    }
    __syncthreads();

    // ---- Phase 3: res (rows 0-63) + skip (rows 64-191)  (M=192, K=64) ----
    {
        float* hdst = h_out + (size_t)b * R * T + t0;
        const float* hsrc = h_in + (size_t)b * R * T + t0;
        float* skp = g_skip + (size_t)b * S * T + t0;
        #pragma unroll
        for (int ui = 0; ui < 3; ui++) {
            int u = wp + ui * 8;
            int slab = u >> 1, nb = (u & 1) * 64;
            float acc[8][4];
            #pragma unroll
            for (int nt = 0; nt < 8; nt++)
                acc[nt][0] = acc[nt][1] = acc[nt][2] = acc[nt][3] = 0.f;
            #pragma unroll 2
            for (int kt = 0; kt < 8; kt++) {
                uint4 Ah = __ldg(&p3h[(slab * 8 + kt) * 32 + l]);
                uint4 Al = __ldg(&p3l[(slab * 8 + kt) * 32 + l]);
                const float* bp = s_hp + (kt * 8 + lk) * AST + ln + nb;
                #pragma unroll
                for (int nt = 0; nt < 8; nt++) {
                    u32 b0 = __float_as_uint(bp[nt * 8]);
                    u32 b1 = __float_as_uint(bp[4 * AST + nt * 8]);
                    MMA(acc[nt], Ah, b0, b1);
                    MMA(acc[nt], Al, b0, b1);
                }
            }
            int r0 = slab * 16 + ln;
            if (r0 < 64) {
                float br0 = __ldg(br + r0), br1 = __ldg(br + r0 + 8);
                #pragma unroll
                for (int nt = 0; nt < 8; nt++) {
                    int c0 = nb + nt * 8 + 2 * lk;
                    float2 h0 = *(const float2*)(hsrc + (size_t)r0 * T + c0);
                    float2 h1 = *(const float2*)(hsrc + (size_t)(r0 + 8) * T + c0);
                    float2 v0 = { acc[nt][0] + br0 + h0.x, acc[nt][1] + br0 + h0.y };
                    float2 v1 = { acc[nt][2] + br1 + h1.x, acc[nt][3] + br1 + h1.y };
                    *(float2*)(hdst + (size_t)r0 * T + c0) = v0;
                    *(float2*)(hdst + (size_t)(r0 + 8) * T + c0) = v1;
                }
            } else {
                int s0 = r0 - 64;
                float bs0 = __ldg(bs + s0), bs1 = __ldg(bs + s0 + 8);
                #pragma unroll
                for (int nt = 0; nt < 8; nt++) {
                    int c0 = nb + nt * 8 + 2 * lk;
                    float2* g0 = (float2*)(skp + (size_t)s0 * T + c0);
                    float2* g1 = (float2*)(skp + (size_t)(s0 + 8) * T + c0);
                    float2 v0 = { acc[nt][0] + bs0, acc[nt][1] + bs0 };
                    float2 v1 = { acc[nt][2] + bs1, acc[nt][3] + bs1 };
                    if (!first) {
                        float2 o0 = *g0, o1 = *g1;
                        v0.x += o0.x; v0.y += o0.y; v1.x += o1.x; v1.y += o1.y;
                    }
                    *g0 = v0; *g1 = v1;
                }
            }
        }
    }
}

// ---------------------------------------------------------------------------
// Kernel 3: head (fp32)
// ---------------------------------------------------------------------------
__global__ void __launch_bounds__(256) head_kernel(
    const float* __restrict__ w1, const float* __restrict__ b1,
    const float* __restrict__ w2, const float* __restrict__ b2,
    float* __restrict__ out)
{
    extern __shared__ float smem[];
    float* sk   = smem;
    float* part = smem + S * TT;

    const int b = blockIdx.y, t0 = blockIdx.x * TT;
    const int tid = threadIdx.x, wp = tid >> 5, l = tid & 31;
    const float* skg = g_skip + (size_t)b * S * T + t0;

    for (int f = tid; f < S * TT / 4; f += 256) {
        int row = f >> 5, col = f & 31;
        float4 v = ((const float4*)(skg + (size_t)row * T))[col];
        v.x = fmaxf(v.x, 0.f); v.y = fmaxf(v.y, 0.f);
        v.z = fmaxf(v.z, 0.f); v.w = fmaxf(v.w, 0.f);
        ((float4*)sk)[f] = v;
    }
    __syncthreads();

    const float4* sk4 = (const float4*)sk;
    float4 po = {0.f, 0.f, 0.f, 0.f};
    for (int s2 = wp * 16; s2 < wp * 16 + 16; s2++) {
        float4 u = {0.f, 0.f, 0.f, 0.f};
        const float* wrow = w1 + (s2 << 7);
        #pragma unroll 8
        for (int s1 = 0; s1 < S; s1++)
            fma4(u, __ldg(wrow + s1), sk4[(s1 << 5) + l]);
        float bb = __ldg(b1 + s2);
        u.x = fmaxf(u.x + bb, 0.f); u.y = fmaxf(u.y + bb, 0.f);
        u.z = fmaxf(u.z + bb, 0.f); u.w = fmaxf(u.w + bb, 0.f);
        fma4(po, __ldg(w2 + s2), u);
    }
    ((float4*)(part + wp * TT))[l] = po;
    __syncthreads();

    if (tid < TT) {
        float acc = __ldg(b2);
        #pragma unroll
        for (int ww = 0; ww < 8; ww++) acc += part[ww * TT + tid];
        out[(size_t)b * T + t0 + tid] = acc;
    }
}

// ---------------------------------------------------------------------------
extern "C" void kernel_launch(void* const* d_in, const int* in_sizes, int n_in,
                              void* d_out, int out_size) {
    const float* x        = (const float*)d_in[0];
    const float* w_in     = (const float*)d_in[1];
    const float* b_in     = (const float*)d_in[2];
    const float* w_causal = (const float*)d_in[3];
    const float* b_causal = (const float*)d_in[4];
    const float* w_filter = (const float*)d_in[5];
    const float* b_filter = (const float*)d_in[6];
    const float* w_gate   = (const float*)d_in[7];
    const float* b_gate   = (const float*)d_in[8];
    const float* w_res    = (const float*)d_in[9];
    const float* b_res    = (const float*)d_in[10];
    const float* w_skip   = (const float*)d_in[11];
    const float* b_skip   = (const float*)d_in[12];
    const float* w_out1   = (const float*)d_in[13];
    const float* b_out1   = (const float*)d_in[14];
    const float* w_out2   = (const float*)d_in[15];
    const float* b_out2   = (const float*)d_in[16];
    float* out = (float*)d_out;

    const int blk_smem  = 3 * 64 * AST * 4;          // ~99 KB
    const int head_smem = (S * TT + 8 * TT) * 4;     // 68 KB
    cudaFuncSetAttribute(block_kernel, cudaFuncAttributeMaxDynamicSharedMemorySize, blk_smem);
    cudaFuncSetAttribute(head_kernel,  cudaFuncAttributeMaxDynamicSharedMemorySize, head_smem);

    float *hbuf0, *p1h, *p1l, *p2h, *p2l, *p3h, *p3l;
    cudaGetSymbolAddress((void**)&hbuf0, g_h);
    cudaGetSymbolAddress((void**)&p1h, g_p1h);
    cudaGetSymbolAddress((void**)&p1l, g_p1l);
    cudaGetSymbolAddress((void**)&p2h, g_p2h);
    cudaGetSymbolAddress((void**)&p2l, g_p2l);
    cudaGetSymbolAddress((void**)&p3h, g_p3h);
    cudaGetSymbolAddress((void**)&p3l, g_p3l);
    float* hbuf[2] = { hbuf0, hbuf0 + (size_t)BB * R * T };

    const int pre_total = NBLK * (P1N + P2N + P3N);
    prep_kernel<<<(pre_total + 255) / 256, 256>>>(w_causal, w_filter, w_gate, w_res, w_skip);

    input_kernel<<<BB * R * T / 256, 256>>>(x, w_in, b_in);

    dim3 grid(T / TT, BB);
    for (int i = 0; i < NBLK; i++) {
        int d = 1 << (i & 7);
        block_kernel<<<grid, 256, blk_smem>>>(
            hbuf[i & 1], hbuf[(i + 1) & 1],
            (const uint4*)(p1h + (size_t)i * P1N), (const uint4*)(p1l + (size_t)i * P1N),
            b_causal + (size_t)i * R,
            (const uint4*)(p2h + (size_t)i * P2N), (const uint4*)(p2l + (size_t)i * P2N),
            b_filter + (size_t)i * R, b_gate + (size_t)i * R,
            (const uint4*)(p3h + (size_t)i * P3N), (const uint4*)(p3l + (size_t)i * P3N),
            b_res + (size_t)i * R, b_skip + (size_t)i * S,
            d, i == 0 ? 1 : 0);
    }

    head_kernel<<<grid, 256, head_smem>>>(w_out1, b_out1, w_out2, b_out2, out);
}